// round 3
// baseline (speedup 1.0000x reference)
#include <cuda_runtime.h>
#include <cstdint>

typedef unsigned long long ull;

#define NROWS 147584   // K_SIZE + B_SIZE
#define KSIZE 147456
#define LATD  512
#define NB    16
#define NFIN  128
#define NFOUT 128
#define HH    64
#define WW    64

// scratch for generated kernels+bias: 16 * 147584 * 4B = 9.45 MB
__device__ float g_ks[NB * NROWS];

// pack two f32 into a 64-bit reg (ALU pipe, dual-issues vs FMA pipe)
#define PK2(dst, a, b) \
  asm("mov.b64 %0, {%1, %2};" : "=l"(dst) : "r"(__float_as_uint(a)), "r"(__float_as_uint(b)))
// packed fp32x2 FMA (FFMA2): 2 FMA per instr, restores 128 FMA/cyc/SM
#define FMA2(acc, a, b) \
  asm("fma.rn.f32x2 %0, %1, %2, %3;" : "=l"(acc) : "l"(a), "l"(b), "l"(acc))

// ---------------------------------------------------------------------------
// Kernel A: ks[b][j] = sum_k lat[b][k] * W[j][k] + bias[j]
// 256 rows per block, row-per-thread. W staged in smem (pad-33 stride ->
// conflict-free compute reads, bank == (t+k) mod 32). lat chunk transposed to
// [k][b] so the 16 batch values per k are 4x LDS128 broadcasts (8 f32x2).
// HBM-bound on W (302 MB). Batches packed in f32x2 pairs.
// ---------------------------------------------------------------------------
#define TJ 256
#define KC 32

__global__ __launch_bounds__(256, 4) void hyper_gemm(
    const float* __restrict__ lat, const float* __restrict__ Wm,
    const float* __restrict__ bias)
{
  __shared__ float Ws[TJ * (KC + 1)];               // [r][k], stride 33
  __shared__ __align__(16) float latc[KC * 16];     // [k][b]
  const int tid = threadIdx.x;
  const int j0 = blockIdx.x * TJ;
  const int j = j0 + tid;

  ull acc[8];
#pragma unroll
  for (int i = 0; i < 8; i++) acc[i] = 0ull;

  for (int kc = 0; kc < LATD; kc += KC) {
    __syncthreads();
    // stage W chunk: rows j0..j0+255, cols kc..kc+KC-1 (coalesced float4 reads)
    {
      const float4* Wg = reinterpret_cast<const float4*>(Wm);
#pragma unroll
      for (int p = 0; p < (TJ * KC / 4) / 256; p++) {   // 8 passes
        int idx4 = p * 256 + tid;
        int r  = idx4 >> 3;      // row within tile
        int kq = idx4 & 7;       // float4 within row chunk
        int jr = j0 + r;
        float4 v = make_float4(0.f, 0.f, 0.f, 0.f);
        if (jr < NROWS) v = Wg[jr * (LATD / 4) + (kc >> 2) + kq];
        float* dst = &Ws[r * (KC + 1) + kq * 4];
        dst[0] = v.x; dst[1] = v.y; dst[2] = v.z; dst[3] = v.w;
      }
    }
    // stage lat chunk transposed: latc[k][b]  (tiny; lat stays L2-resident)
    for (int idx = tid; idx < KC * 16; idx += 256) {
      int kl = idx >> 4;
      int bb = idx & 15;
      latc[kl * 16 + bb] = lat[bb * LATD + kc + kl];
    }
    __syncthreads();

    const ulonglong2* latp = reinterpret_cast<const ulonglong2*>(latc);
#pragma unroll
    for (int k = 0; k < KC; k++) {
      float wv = Ws[tid * (KC + 1) + k];
      ull w2; PK2(w2, wv, wv);
#pragma unroll
      for (int q = 0; q < 4; q++) {
        ulonglong2 lv = latp[k * 4 + q];   // 4 batch-pairs per LDS128 broadcast
        FMA2(acc[2 * q + 0], w2, lv.x);
        FMA2(acc[2 * q + 1], w2, lv.y);
      }
    }
  }

  if (j < NROWS) {
    float bv = bias[j];
#pragma unroll
    for (int p = 0; p < 8; p++) {
      float2 v = *reinterpret_cast<float2*>(&acc[p]);
      g_ks[(2 * p + 0) * NROWS + j] = v.x + bv;
      g_ks[(2 * p + 1) * NROWS + j] = v.y + bv;
    }
  }
}

// ---------------------------------------------------------------------------
// Kernel B: per-sample 3x3 conv with generated kernels, all in f32x2.
// Block(256) covers: b fixed, 32 fout x 4 rows x 64 cols.
//   warp w: row = w&3, fout-half = w>>2 (16 fouts each)
//   lane l: cols {l, l+32}  -> consecutive-lane smem reads, conflict-free
// acc: 8 fout-pairs (f32x2) x 2 cols = 16 ull accumulators.
// FIN chunked by 16: ws[tap][fo] (stride 36, 16B-aligned broadcasts),
// xs[fi][6 rows][68] with halo+pad.
// ---------------------------------------------------------------------------
#define FC 16

__global__ __launch_bounds__(256, 2) void dyn_conv(
    const float* __restrict__ x, float* __restrict__ out)
{
  __shared__ __align__(16) float ws[FC * 9 * 36];   // [r=fi*9+tap][fo], 20.25 KB
  __shared__ float xs[FC * 6 * 68];                 // [fi][rr][cx], 25.5 KB
  const int tid  = threadIdx.x;
  const int lane = tid & 31;
  const int wrp  = tid >> 5;
  const int row  = wrp & 3;      // output row within tile
  const int foh  = wrp >> 2;     // 0/1 -> which 16-fout half
  const int b    = blockIdx.z;
  const int fog  = blockIdx.y;   // fout group of 32
  const int rt   = blockIdx.x;   // row tile (4 rows)
  const int grow0 = rt * 4 - 1;

  ull acc[16];
#pragma unroll
  for (int i = 0; i < 16; i++) acc[i] = 0ull;

  const float* kbase = g_ks + b * NROWS + fog * 32 * 1152;
  const float* xbase = x + (b * NFIN) * (HH * WW);

  for (int fc = 0; fc < NFIN; fc += FC) {
    __syncthreads();
    // stage weights: 32 fouts x FC fins x 9 taps  (contiguous 144-float runs)
    for (int idx = tid; idx < 32 * FC * 9; idx += 256) {
      int fo = idx / (FC * 9);
      int r  = idx - fo * (FC * 9);       // fi*9 + tap
      ws[r * 36 + fo] = kbase[fo * 1152 + fc * 9 + r];
    }
    // stage x tile with halo: rows grow0..grow0+5, cols -1..64
    for (int idx = tid; idx < FC * 6 * 66; idx += 256) {
      int fi  = idx / 396;
      int rem = idx - fi * 396;
      int rr  = rem / 66;
      int cx  = rem - rr * 66;
      int gr  = grow0 + rr;
      int gc  = cx - 1;
      float v = 0.f;
      if ((unsigned)gr < (unsigned)HH && (unsigned)gc < (unsigned)WW)
        v = xbase[(fc + fi) * (HH * WW) + gr * WW + gc];
      xs[fi * 408 + rr * 68 + cx] = v;
    }
    __syncthreads();

#pragma unroll 2
    for (int fi = 0; fi < FC; fi++) {
      const float* xrow0 = &xs[fi * 408];
      const float* wsb   = &ws[fi * 9 * 36 + foh * 16];
#pragma unroll
      for (int kh = 0; kh < 3; kh++) {
        const float* xr = xrow0 + (row + kh) * 68 + lane;
        float xa0 = xr[0],  xa1 = xr[1],  xa2 = xr[2];
        float xb0 = xr[32], xb1 = xr[33], xb2 = xr[34];
        ull xpa[3], xpb[3];
        PK2(xpa[0], xa0, xa0); PK2(xpa[1], xa1, xa1); PK2(xpa[2], xa2, xa2);
        PK2(xpb[0], xb0, xb0); PK2(xpb[1], xb1, xb1); PK2(xpb[2], xb2, xb2);
#pragma unroll
        for (int kw = 0; kw < 3; kw++) {
          const float4* wq = reinterpret_cast<const float4*>(wsb + (kh * 3 + kw) * 36);
          float4 wA = wq[0], wB = wq[1], wC = wq[2], wD = wq[3];  // 16 fouts
          ull w2[8];
          PK2(w2[0], wA.x, wA.y); PK2(w2[1], wA.z, wA.w);
          PK2(w2[2], wB.x, wB.y); PK2(w2[3], wB.z, wB.w);
          PK2(w2[4], wC.x, wC.y); PK2(w2[5], wC.z, wC.w);
          PK2(w2[6], wD.x, wD.y); PK2(w2[7], wD.z, wD.w);
#pragma unroll
          for (int p = 0; p < 8; p++) {
            FMA2(acc[2 * p + 0], w2[p], xpa[kw]);   // col = lane
            FMA2(acc[2 * p + 1], w2[p], xpb[kw]);   // col = lane + 32
          }
        }
      }
    }
  }

  // epilogue: add bias, store (coalesced per fout row)
  const int gr  = rt * 4 + row;
  const int fo0 = fog * 32 + foh * 16;
  const int obase = (b * NFOUT) * (HH * WW);
  const float* biasb = g_ks + b * NROWS + KSIZE;
#pragma unroll
  for (int p = 0; p < 8; p++) {
    float2 v0 = *reinterpret_cast<float2*>(&acc[2 * p + 0]);
    float2 v1 = *reinterpret_cast<float2*>(&acc[2 * p + 1]);
    int foA = fo0 + 2 * p;
    int foB = foA + 1;
    float bA = biasb[foA];
    float bB = biasb[foB];
    out[obase + foA * (HH * WW) + gr * WW + lane]      = v0.x + bA;
    out[obase + foA * (HH * WW) + gr * WW + lane + 32] = v1.x + bA;
    out[obase + foB * (HH * WW) + gr * WW + lane]      = v0.y + bB;
    out[obase + foB * (HH * WW) + gr * WW + lane + 32] = v1.y + bB;
  }
}

// ---------------------------------------------------------------------------
extern "C" void kernel_launch(void* const* d_in, const int* in_sizes, int n_in,
                              void* d_out, int out_size) {
  const float* x   = (const float*)d_in[0];   // [16,128,64,64]
  const float* lat = (const float*)d_in[1];   // [16,512]
  const float* Wm  = (const float*)d_in[2];   // [147584,512]
  const float* bv  = (const float*)d_in[3];   // [147584]
  float* out = (float*)d_out;                 // [16,128,64,64]

  hyper_gemm<<<(NROWS + TJ - 1) / TJ, 256>>>(lat, Wm, bv);

  dim3 g(HH / 4, NFOUT / 32, NB);             // 16 x 4 x 16 = 1024 blocks
  dyn_conv<<<g, 256>>>(x, out);
}

// round 7
// speedup vs baseline: 1.3395x; 1.3395x over previous
#include <cuda_runtime.h>
#include <cuda_bf16.h>
#include <cstdint>

typedef unsigned long long ull;

#define NROWS 147584
#define KSIZE 147456
#define LATD  512
#define NB    16
#define NFIN  128
#define NFOUT 128
#define HH    64
#define WW    64
#define PLANE (66 * 68)

// split-bf16 weights, k-reordered: k' = tap*128 + fi
__device__ __nv_bfloat16 g_kahi[NB * KSIZE];        // 4.72 MB
__device__ __nv_bfloat16 g_kalo[NB * KSIZE];        // 4.72 MB
__device__ float         g_bias[NB * NFOUT];
// split-bf16 x, zero-padded planes [66][68] (input (r,c) -> padded (r+1,c+1))
__device__ __nv_bfloat16 g_xhi[NB * NFIN * PLANE];  // 18.4 MB
__device__ __nv_bfloat16 g_xlo[NB * NFIN * PLANE];  // 18.4 MB

// ---------------- f32x2 helpers (hyper_gemm) ----------------
#define PK2(dst, a, b) \
  asm("mov.b64 %0, {%1, %2};" : "=l"(dst) : "r"(__float_as_uint(a)), "r"(__float_as_uint(b)))
#define FMA2(acc, a, b) \
  asm("fma.rn.f32x2 %0, %1, %2, %3;" : "=l"(acc) : "l"(a), "l"(b), "l"(acc))

// ---------------- cp.async ----------------
#define CPA4(dst, src) \
  asm volatile("cp.async.ca.shared.global [%0], [%1], 4;" :: "r"(dst), "l"(src))
#define CPCOMMIT() asm volatile("cp.async.commit_group;" ::: "memory")
#define CPWAIT1()  asm volatile("cp.async.wait_group 1;" ::: "memory")
#define CPWAIT0()  asm volatile("cp.async.wait_group 0;" ::: "memory")

__device__ __forceinline__ uint32_t smem_u32(const void* p) {
  uint32_t a;
  asm("{ .reg .u64 t; cvta.to.shared.u64 t, %1; cvt.u32.u64 %0, t; }" : "=r"(a) : "l"(p));
  return a;
}

// ---------------- warp-MMA helpers (sm_80 baseline PTX -> HMMA/LDSM) -------
#define LDSM4(r0, r1, r2, r3, addr) \
  asm volatile("ldmatrix.sync.aligned.m8n8.x4.shared.b16 {%0,%1,%2,%3}, [%4];" \
               : "=r"(r0), "=r"(r1), "=r"(r2), "=r"(r3) : "r"(addr))
#define LDSM4T(r0, r1, r2, r3, addr) \
  asm volatile("ldmatrix.sync.aligned.m8n8.x4.trans.shared.b16 {%0,%1,%2,%3}, [%4];" \
               : "=r"(r0), "=r"(r1), "=r"(r2), "=r"(r3) : "r"(addr))
#define MMA16816(c, a, b0, b1) \
  asm volatile("mma.sync.aligned.m16n8k16.row.col.f32.bf16.bf16.f32 " \
               "{%0,%1,%2,%3}, {%4,%5,%6,%7}, {%8,%9}, {%0,%1,%2,%3};" \
               : "+f"((c)[0]), "+f"((c)[1]), "+f"((c)[2]), "+f"((c)[3]) \
               : "r"((a)[0]), "r"((a)[1]), "r"((a)[2]), "r"((a)[3]), \
                 "r"(b0), "r"(b1))

// ===========================================================================
// Kernel 0: split x -> bf16 hi/lo padded planes (borders zero)
// ===========================================================================
__global__ __launch_bounds__(256) void xsplit(const float* __restrict__ x) {
  const int plane = blockIdx.y;                      // b*128 + fi
  const int i = blockIdx.x * 256 + threadIdx.x;      // 0..4487
  if (i >= PLANE) return;
  const int rp = i / 68, cp = i - rp * 68;
  const int r = rp - 1, c = cp - 1;
  float v = 0.f;
  if ((unsigned)r < (unsigned)HH && (unsigned)c < (unsigned)WW)
    v = x[(size_t)plane * (HH * WW) + r * WW + c];
  __nv_bfloat16 h = __float2bfloat16(v);
  __nv_bfloat16 l = __float2bfloat16(v - __bfloat162float(h));
  g_xhi[(size_t)plane * PLANE + i] = h;
  g_xlo[(size_t)plane * PLANE + i] = l;
}

// ===========================================================================
// Kernel A: hyper GEMM, cp.async double-buffered. Epilogue emits split-bf16
// weights in k' = tap*128+fi order plus bias array.
// ===========================================================================
#define HKC  16
#define HWST 17
#define HBUF (256 * HWST)
#define HSMEM ((2 * HBUF + 512 * 16) * 4)    // 67584 B

__global__ __launch_bounds__(256) void hyper_gemm(
    const float* __restrict__ lat, const float* __restrict__ Wm,
    const float* __restrict__ bias)
{
  extern __shared__ __align__(16) float hsm[];
  float* Ws = hsm;
  float* latc = hsm + 2 * HBUF;
  const uint32_t wsb = smem_u32(Ws);
  const int tid = threadIdx.x;
  const int j0 = blockIdx.x * 256;
  const int j = j0 + tid;

  ull acc[8];
#pragma unroll
  for (int i = 0; i < 8; i++) acc[i] = 0ull;

  for (int idx = tid; idx < LATD * 16; idx += 256)
    latc[idx] = lat[(idx & 15) * LATD + (idx >> 4)];

#pragma unroll
  for (int p = 0; p < 16; p++) {
    int idx = p * 256 + tid;
    int r = idx >> 4, k = idx & 15;
    int jr = j0 + r;
    if (jr < NROWS)
      CPA4(wsb + (uint32_t)(r * HWST + k) * 4, Wm + (size_t)jr * LATD + k);
  }
  CPCOMMIT();

  int buf = 0;
  for (int c = 0; c < LATD / HKC; c++) {
    if (c + 1 < LATD / HKC) {
#pragma unroll
      for (int p = 0; p < 16; p++) {
        int idx = p * 256 + tid;
        int r = idx >> 4, k = idx & 15;
        int jr = j0 + r;
        if (jr < NROWS)
          CPA4(wsb + (uint32_t)((buf ^ 1) * HBUF + r * HWST + k) * 4,
               Wm + (size_t)jr * LATD + (c + 1) * HKC + k);
      }
      CPCOMMIT();
      CPWAIT1();
    } else {
      CPWAIT0();
    }
    __syncthreads();

    const ulonglong2* latp = reinterpret_cast<const ulonglong2*>(latc);
    const float* wr = &Ws[buf * HBUF + tid * HWST];
#pragma unroll
    for (int k = 0; k < HKC; k++) {
      float wv = wr[k];
      ull w2; PK2(w2, wv, wv);
      int kk = c * HKC + k;
#pragma unroll
      for (int q = 0; q < 4; q++) {
        ulonglong2 lv = latp[kk * 4 + q];
        FMA2(acc[2 * q + 0], w2, lv.x);
        FMA2(acc[2 * q + 1], w2, lv.y);
      }
    }
    buf ^= 1;
    __syncthreads();
  }

  if (j < KSIZE) {
    int fo = j / 1152;
    int rem = j - fo * 1152;
    int fi = rem / 9;
    int tap = rem - fi * 9;
    size_t dst = (size_t)fo * 1152 + tap * 128 + fi;
    float bv = bias[j];
#pragma unroll
    for (int p = 0; p < 8; p++) {
      float2 v = *reinterpret_cast<float2*>(&acc[p]);
      float va = v.x + bv, vb = v.y + bv;
      __nv_bfloat16 ha = __float2bfloat16(va);
      __nv_bfloat16 la = __float2bfloat16(va - __bfloat162float(ha));
      __nv_bfloat16 hb = __float2bfloat16(vb);
      __nv_bfloat16 lb = __float2bfloat16(vb - __bfloat162float(hb));
      g_kahi[(size_t)(2 * p + 0) * KSIZE + dst] = ha;
      g_kalo[(size_t)(2 * p + 0) * KSIZE + dst] = la;
      g_kahi[(size_t)(2 * p + 1) * KSIZE + dst] = hb;
      g_kalo[(size_t)(2 * p + 1) * KSIZE + dst] = lb;
    }
  } else if (j < NROWS) {
    int fo = j - KSIZE;
    float bv = bias[j];
#pragma unroll
    for (int p = 0; p < 8; p++) {
      float2 v = *reinterpret_cast<float2*>(&acc[p]);
      g_bias[(2 * p + 0) * NFOUT + fo] = v.x + bv;
      g_bias[(2 * p + 1) * NFOUT + fo] = v.y + bv;
    }
  }
}

// ===========================================================================
// Kernel B: warp-MMA (HMMA) split-bf16 implicit-GEMM conv.
// CTA = (sample, 128-px tile). 8 warps: warp (wm,wn) owns M64 x N32.
// 72 k-steps (9 taps x 8 fi-chunks of 16). 3 split passes per k-step.
// A [128m][16k] stride 24 (ldmatrix, conflict-free); B [16k][128n] stride 136
// (ldmatrix.trans, conflict-free).
// ldmatrix.x4 register order follows ADDRESS GROUPS: r0=lanes0-7, r1=lanes8-15,
// r2=lanes16-23, r3=lanes24-31. With bRow addressing that is:
//   r0=(k0-7,n0-7) r1=(k8-15,n0-7) r2=(k0-7,n8-15) r3=(k8-15,n8-15)
// => for n-group j: b0 = b[2j], b1 = b[2j+1].   (R5 bug: used wrong pairing)
// ===========================================================================
#define SA 24
#define SB 136

__global__ __launch_bounds__(256, 2) void conv_mma(float* __restrict__ out) {
  __shared__ __align__(16) __nv_bfloat16 sAhi[128 * SA];  // 6144 B
  __shared__ __align__(16) __nv_bfloat16 sAlo[128 * SA];
  __shared__ __align__(16) __nv_bfloat16 sBhi[16 * SB];   // 4352 B
  __shared__ __align__(16) __nv_bfloat16 sBlo[16 * SB];
  __shared__ float sbias[NFOUT];

  const int tid = threadIdx.x;
  const int lane = tid & 31, wid = tid >> 5;
  const int wm = wid >> 2;          // 0..1  m-half (64 fouts)
  const int wn = wid & 3;           // 0..3  n-quarter (32 px)
  const int t = blockIdx.x;         // px tile: output rows 2t, 2t+1
  const int b = blockIdx.y;
  const int r0 = t * 2;

  float acc[4][4][4];
#pragma unroll
  for (int f = 0; f < 4; f++)
#pragma unroll
    for (int j = 0; j < 4; j++)
#pragma unroll
      for (int q = 0; q < 4; q++) acc[f][j][q] = 0.f;

  if (tid < NFOUT) sbias[tid] = g_bias[b * NFOUT + tid];

  const __nv_bfloat16* kah = g_kahi + (size_t)b * KSIZE;
  const __nv_bfloat16* kal = g_kalo + (size_t)b * KSIZE;
  const __nv_bfloat16* xph = g_xhi + (size_t)(b * NFIN) * PLANE;
  const __nv_bfloat16* xpl = g_xlo + (size_t)(b * NFIN) * PLANE;

  // per-lane ldmatrix addresses (row part fixed, tile base varies)
  const uint32_t aHb = smem_u32(sAhi), aLb = smem_u32(sAlo);
  const uint32_t bHb = smem_u32(sBhi), bLb = smem_u32(sBlo);
  const uint32_t aRow = (uint32_t)(((wm * 64 + (lane & 15)) * SA + 8 * (lane >> 4)) * 2);
  const uint32_t bRow = (uint32_t)(((lane & 15) * SB + wn * 32 + 8 * (lane >> 4)) * 2);

  for (int tap = 0; tap < 9; tap++) {
    const int dy = tap / 3 - 1;
    const int dx1 = tap % 3;                 // dx + 1 in {0,1,2}
    const int rbase = r0 + dy + 1;           // padded row of py=0
    for (int fc = 0; fc < 8; fc++) {
      __syncthreads();
      // ---- stage A: [128][16] hi/lo, 16B vector loads ----
      {
        const int kofs = tap * 128 + fc * 16;
#pragma unroll
        for (int rep = 0; rep < 2; rep++) {
          int i = rep * 256 + tid;
          int arr = i >> 8, rem = i & 255, r = rem >> 1, h = rem & 1;
          const uint4* src = reinterpret_cast<const uint4*>(
              (arr ? kal : kah) + (size_t)r * 1152 + kofs + h * 8);
          uint4 v = *src;
          *reinterpret_cast<uint4*>((arr ? sAlo : sAhi) + r * SA + h * 8) = v;
        }
      }
      // ---- stage B: [16 k=fi][128 n=px] hi/lo from padded planes ----
      {
        const int fib = fc * 16;
        if (dx1 != 1) {  // even shift -> aligned u32 pair loads
#pragma unroll
          for (int rep = 0; rep < 8; rep++) {
            int i = rep * 256 + tid;
            int arr = i >> 10, rem = i & 1023;
            int fi = rem >> 6, r2 = rem & 63, py = r2 >> 5, cp = r2 & 31;
            size_t so = (size_t)(fib + fi) * PLANE + (size_t)(rbase + py) * 68 + (2 * cp + dx1);
            uint32_t v = *reinterpret_cast<const uint32_t*>((arr ? xpl : xph) + so);
            *reinterpret_cast<uint32_t*>((arr ? sBlo : sBhi) + fi * SB + py * 64 + 2 * cp) = v;
          }
        } else {         // odd shift -> two u16 loads
#pragma unroll
          for (int rep = 0; rep < 8; rep++) {
            int i = rep * 256 + tid;
            int arr = i >> 10, rem = i & 1023;
            int fi = rem >> 6, r2 = rem & 63, py = r2 >> 5, cp = r2 & 31;
            const __nv_bfloat16* sp =
                (arr ? xpl : xph) + (size_t)(fib + fi) * PLANE + (size_t)(rbase + py) * 68 + (2 * cp + 1);
            uint32_t v0 = *reinterpret_cast<const uint16_t*>(sp);
            uint32_t v1 = *reinterpret_cast<const uint16_t*>(sp + 1);
            *reinterpret_cast<uint32_t*>((arr ? sBlo : sBhi) + fi * SB + py * 64 + 2 * cp) =
                v0 | (v1 << 16);
          }
        }
      }
      __syncthreads();

      // ---- compute: 3 split passes ----
      uint32_t a[4][4], bh[8], bl[8];
#pragma unroll
      for (int f = 0; f < 4; f++)
        LDSM4(a[f][0], a[f][1], a[f][2], a[f][3], aHb + aRow + (uint32_t)(f * 16 * SA * 2));
#pragma unroll
      for (int g = 0; g < 2; g++)
        LDSM4T(bh[4 * g + 0], bh[4 * g + 1], bh[4 * g + 2], bh[4 * g + 3],
               bHb + bRow + (uint32_t)(g * 16 * 2));
#pragma unroll
      for (int f = 0; f < 4; f++)
#pragma unroll
        for (int j = 0; j < 4; j++)
          MMA16816(acc[f][j], a[f], bh[2 * j], bh[2 * j + 1]);

#pragma unroll
      for (int g = 0; g < 2; g++)
        LDSM4T(bl[4 * g + 0], bl[4 * g + 1], bl[4 * g + 2], bl[4 * g + 3],
               bLb + bRow + (uint32_t)(g * 16 * 2));
#pragma unroll
      for (int f = 0; f < 4; f++)
#pragma unroll
        for (int j = 0; j < 4; j++)
          MMA16816(acc[f][j], a[f], bl[2 * j], bl[2 * j + 1]);

#pragma unroll
      for (int f = 0; f < 4; f++)
        LDSM4(a[f][0], a[f][1], a[f][2], a[f][3], aLb + aRow + (uint32_t)(f * 16 * SA * 2));
#pragma unroll
      for (int f = 0; f < 4; f++)
#pragma unroll
        for (int j = 0; j < 4; j++)
          MMA16816(acc[f][j], a[f], bh[2 * j], bh[2 * j + 1]);
    }
  }

  // ---- epilogue: bias + store (float2 per frag row) ----
  float* ob = out + (size_t)b * (NFOUT * HH * WW) + t * 128;
#pragma unroll
  for (int f = 0; f < 4; f++) {
    int fo0 = wm * 64 + f * 16 + (lane >> 2);
    float bv0 = sbias[fo0], bv1 = sbias[fo0 + 8];
#pragma unroll
    for (int j = 0; j < 4; j++) {
      int n = wn * 32 + j * 8 + 2 * (lane & 3);
      float2 v0 = make_float2(acc[f][j][0] + bv0, acc[f][j][1] + bv0);
      float2 v1 = make_float2(acc[f][j][2] + bv1, acc[f][j][3] + bv1);
      *reinterpret_cast<float2*>(ob + (size_t)fo0 * (HH * WW) + n) = v0;
      *reinterpret_cast<float2*>(ob + (size_t)(fo0 + 8) * (HH * WW) + n) = v1;
    }
  }
}

// ===========================================================================
extern "C" void kernel_launch(void* const* d_in, const int* in_sizes, int n_in,
                              void* d_out, int out_size) {
  const float* x   = (const float*)d_in[0];
  const float* lat = (const float*)d_in[1];
  const float* Wm  = (const float*)d_in[2];
  const float* bv  = (const float*)d_in[3];
  float* out = (float*)d_out;

  cudaFuncSetAttribute(hyper_gemm, cudaFuncAttributeMaxDynamicSharedMemorySize, HSMEM);

  dim3 gx((PLANE + 255) / 256, NB * NFIN);
  xsplit<<<gx, 256>>>(x);

  hyper_gemm<<<(NROWS + 255) / 256, 256, HSMEM>>>(lat, Wm, bv);

  dim3 g(HH * WW / 128, NB);   // 32 x 16 = 512 CTAs
  conv_mma<<<g, 256>>>(out);
}

// round 8
// speedup vs baseline: 1.7329x; 1.2936x over previous
#include <cuda_runtime.h>
#include <cuda_fp16.h>
#include <cstdint>

typedef unsigned long long ull;

#define NROWS 147584
#define KSIZE 147456
#define LATD  512
#define NB    16
#define NFIN  128
#define NFOUT 128
#define HH    64
#define WW    64

// split-fp16 weights, k-reordered: k' = tap*128 + fi
__device__ __align__(16) __half g_kh[NB * KSIZE];   // 4.72 MB
__device__ __align__(16) __half g_kl[NB * KSIZE];   // 4.72 MB
__device__ float g_bias[NB * NFOUT];

// ---------------- f32x2 helpers (hyper_gemm) ----------------
#define PK2(dst, a, b) \
  asm("mov.b64 %0, {%1, %2};" : "=l"(dst) : "r"(__float_as_uint(a)), "r"(__float_as_uint(b)))
#define FMA2(acc, a, b) \
  asm("fma.rn.f32x2 %0, %1, %2, %3;" : "=l"(acc) : "l"(a), "l"(b), "l"(acc))

// ---------------- cp.async ----------------
#define CPA4(dst, src) \
  asm volatile("cp.async.ca.shared.global [%0], [%1], 4;" :: "r"(dst), "l"(src))
#define CPA16(dst, src) \
  asm volatile("cp.async.cg.shared.global [%0], [%1], 16;" :: "r"(dst), "l"(src))
#define CPCOMMIT() asm volatile("cp.async.commit_group;" ::: "memory")
#define CPWAIT1()  asm volatile("cp.async.wait_group 1;" ::: "memory")
#define CPWAIT0()  asm volatile("cp.async.wait_group 0;" ::: "memory")

__device__ __forceinline__ uint32_t smem_u32(const void* p) {
  uint32_t a;
  asm("{ .reg .u64 t; cvta.to.shared.u64 t, %1; cvt.u32.u64 %0, t; }" : "=r"(a) : "l"(p));
  return a;
}

// ---------------- warp-MMA helpers ----------------
#define LDSM4(r0, r1, r2, r3, addr) \
  asm volatile("ldmatrix.sync.aligned.m8n8.x4.shared.b16 {%0,%1,%2,%3}, [%4];" \
               : "=r"(r0), "=r"(r1), "=r"(r2), "=r"(r3) : "r"(addr))
#define MMA16816(c, a, b0, b1) \
  asm volatile("mma.sync.aligned.m16n8k16.row.col.f32.f16.f16.f32 " \
               "{%0,%1,%2,%3}, {%4,%5,%6,%7}, {%8,%9}, {%0,%1,%2,%3};" \
               : "+f"((c)[0]), "+f"((c)[1]), "+f"((c)[2]), "+f"((c)[3]) \
               : "r"((a)[0]), "r"((a)[1]), "r"((a)[2]), "r"((a)[3]), \
                 "r"(b0), "r"(b1))

// ===========================================================================
// Kernel A: hyper GEMM, cp.async double-buffered. Epilogue emits split-fp16
// weights in k' = tap*128+fi order plus f32 bias array.
// ===========================================================================
#define HKC  16
#define HWST 17
#define HBUF (256 * HWST)
#define HSMEM ((2 * HBUF + 512 * 16) * 4)    // 67584 B

__global__ __launch_bounds__(256) void hyper_gemm(
    const float* __restrict__ lat, const float* __restrict__ Wm,
    const float* __restrict__ bias)
{
  extern __shared__ __align__(16) float hsm[];
  float* Ws = hsm;
  float* latc = hsm + 2 * HBUF;
  const uint32_t wsb = smem_u32(Ws);
  const int tid = threadIdx.x;
  const int j0 = blockIdx.x * 256;
  const int j = j0 + tid;

  ull acc[8];
#pragma unroll
  for (int i = 0; i < 8; i++) acc[i] = 0ull;

  for (int idx = tid; idx < LATD * 16; idx += 256)
    latc[idx] = lat[(idx & 15) * LATD + (idx >> 4)];

#pragma unroll
  for (int p = 0; p < 16; p++) {
    int idx = p * 256 + tid;
    int r = idx >> 4, k = idx & 15;
    int jr = j0 + r;
    if (jr < NROWS)
      CPA4(wsb + (uint32_t)(r * HWST + k) * 4, Wm + (size_t)jr * LATD + k);
  }
  CPCOMMIT();

  int buf = 0;
  for (int c = 0; c < LATD / HKC; c++) {
    if (c + 1 < LATD / HKC) {
#pragma unroll
      for (int p = 0; p < 16; p++) {
        int idx = p * 256 + tid;
        int r = idx >> 4, k = idx & 15;
        int jr = j0 + r;
        if (jr < NROWS)
          CPA4(wsb + (uint32_t)((buf ^ 1) * HBUF + r * HWST + k) * 4,
               Wm + (size_t)jr * LATD + (c + 1) * HKC + k);
      }
      CPCOMMIT();
      CPWAIT1();
    } else {
      CPWAIT0();
    }
    __syncthreads();

    const ulonglong2* latp = reinterpret_cast<const ulonglong2*>(latc);
    const float* wr = &Ws[buf * HBUF + tid * HWST];
#pragma unroll
    for (int k = 0; k < HKC; k++) {
      float wv = wr[k];
      ull w2; PK2(w2, wv, wv);
      int kk = c * HKC + k;
#pragma unroll
      for (int q = 0; q < 4; q++) {
        ulonglong2 lv = latp[kk * 4 + q];
        FMA2(acc[2 * q + 0], w2, lv.x);
        FMA2(acc[2 * q + 1], w2, lv.y);
      }
    }
    buf ^= 1;
    __syncthreads();
  }

  if (j < KSIZE) {
    int fo = j / 1152;
    int rem = j - fo * 1152;
    int fi = rem / 9;
    int tap = rem - fi * 9;
    size_t dst = (size_t)fo * 1152 + tap * 128 + fi;
    float bv = bias[j];
#pragma unroll
    for (int p = 0; p < 8; p++) {
      float2 v = *reinterpret_cast<float2*>(&acc[p]);
      float va = v.x + bv, vb = v.y + bv;
      __half ha = __float2half(va);
      __half la = __float2half(va - __half2float(ha));
      __half hb = __float2half(vb);
      __half lb = __float2half(vb - __half2float(hb));
      g_kh[(size_t)(2 * p + 0) * KSIZE + dst] = ha;
      g_kl[(size_t)(2 * p + 0) * KSIZE + dst] = la;
      g_kh[(size_t)(2 * p + 1) * KSIZE + dst] = hb;
      g_kl[(size_t)(2 * p + 1) * KSIZE + dst] = lb;
    }
  } else if (j < NROWS) {
    int fo = j - KSIZE;
    float bv = bias[j];
#pragma unroll
    for (int p = 0; p < 8; p++) {
      float2 v = *reinterpret_cast<float2*>(&acc[p]);
      g_bias[(2 * p + 0) * NFOUT + fo] = v.x + bv;
      g_bias[(2 * p + 1) * NFOUT + fo] = v.y + bv;
    }
  }
}

// ===========================================================================
// Kernel B: warp-MMA fp16 2-pass implicit-GEMM conv.
// CTA = (sample b, 128-px tile = out rows 2t..2t+1). 8 warps M64xN32 each.
// Outer loop: 8 fi-chunks of 16. Per chunk: stage x tile ONCE
// ([4 padded rows x 68 cols][16 fi], 36B cells, bank-stride 9), reused by all
// 9 taps. Inner loop: 9 taps; A (w_hi,w_lo) double-buffered via cp.async.
// B fragments via direct LDS.32 (2 consecutive fi per reg = fragment layout).
// Passes: w_hi * x, w_lo * x  (x single fp16; err ~2.8e-4 global).
// ===========================================================================
#define CS   36                       // bytes per (row,col) cell (16 fp16 + 4 pad)
#define XTB  (272 * CS)               // 9792 B
#define SA_B 48                       // bytes per A row (32B data + 16 pad)
#define AHL  (128 * SA_B)             // 6144 B (one hi or lo tile)
#define ABUF (2 * AHL)                // 12288 B (hi+lo, one buffer)

__global__ __launch_bounds__(256, 2) void conv_mma(
    const float* __restrict__ x, float* __restrict__ out)
{
  __shared__ __align__(16) unsigned char sxt[XTB];          // x tile (fp16)
  __shared__ __align__(16) unsigned char sA[2 * ABUF];      // w tiles, dbl-buf
  __shared__ float sbias[NFOUT];

  const int tid = threadIdx.x;
  const int lane = tid & 31, wid = tid >> 5;
  const int wm = wid >> 2;          // m-half (64 fouts)
  const int wn = wid & 3;           // n-quarter (32 px)
  const int t = blockIdx.x;         // out rows 2t, 2t+1
  const int b = blockIdx.y;

  float acc[4][4][4];
#pragma unroll
  for (int f = 0; f < 4; f++)
#pragma unroll
    for (int j = 0; j < 4; j++)
#pragma unroll
      for (int q = 0; q < 4; q++) acc[f][j][q] = 0.f;

  if (tid < NFOUT) sbias[tid] = g_bias[b * NFOUT + tid];

  const __half* kh = g_kh + (size_t)b * KSIZE;
  const __half* kl = g_kl + (size_t)b * KSIZE;
  const float* xb = x + (size_t)(b * NFIN) * (HH * WW);

  const uint32_t sxb = smem_u32(sxt);
  const uint32_t sab = smem_u32(sA);
  const uint32_t aRow = (uint32_t)((wm * 64 + (lane & 15)) * SA_B + (lane >> 4) * 16);

  // per-lane B-fragment cell indices (loop-invariant part)
  int pj[4];
#pragma unroll
  for (int j = 0; j < 4; j++) {
    int px = wn * 32 + j * 8 + (lane >> 2);
    pj[j] = (px >> 6) * 68 + (px & 63);
  }
  const uint32_t bOff = (uint32_t)((lane & 3) * 4);

  // prologue: issue A(0) -> buf 0
  {
    const int kofs = 0 * 128 + 0 * 16;
#pragma unroll
    for (int p = 0; p < 2; p++) {
      int i = p * 256 + tid;
      int hl = i >> 8, rem = i & 255, r = rem >> 1, ch = rem & 1;
      const __half* src = (hl ? kl : kh) + (size_t)r * 1152 + kofs + ch * 8;
      CPA16(sab + (uint32_t)(hl * AHL + r * SA_B + ch * 16), src);
    }
    CPCOMMIT();
  }

  int s = 0;
  for (int fc = 0; fc < 8; fc++) {
    __syncthreads();   // all warps done computing on previous x tile
    // ---- stage x tile: rows 2t..2t+3 (padded), cols 0..67, fi chunk ----
    {
      const int fib = fc * 16;
#pragma unroll
      for (int p = 0; p < 17; p++) {
        int i = p * 256 + tid;
        int fi = i / 272, cell = i - fi * 272;
        int r = cell / 68, c = cell - r * 68;
        int gr = 2 * t + r;            // padded row
        float v = 0.f;
        if ((unsigned)(gr - 1) < (unsigned)HH && (unsigned)(c - 1) < (unsigned)WW)
          v = xb[(size_t)(fib + fi) * (HH * WW) + (gr - 1) * WW + (c - 1)];
        *reinterpret_cast<__half*>(sxt + cell * CS + fi * 2) = __float2half(v);
      }
    }
    for (int tap = 0; tap < 9; tap++, s++) {
      const int buf = s & 1;
      __syncthreads();   // prev compute done -> safe to fill buf^1; x stores done
      if (s + 1 < 72) {
        // issue A(s+1): next (fc,tap) in flattened order
        int s1 = s + 1;
        int fc1 = s1 / 9, tap1 = s1 - fc1 * 9;
        const int kofs = tap1 * 128 + fc1 * 16;
#pragma unroll
        for (int p = 0; p < 2; p++) {
          int i = p * 256 + tid;
          int hl = i >> 8, rem = i & 255, r = rem >> 1, ch = rem & 1;
          const __half* src = (hl ? kl : kh) + (size_t)r * 1152 + kofs + ch * 8;
          CPA16(sab + (uint32_t)((buf ^ 1) * ABUF + hl * AHL + r * SA_B + ch * 16), src);
        }
        CPCOMMIT();
        CPWAIT1();
      } else {
        CPWAIT0();
      }
      __syncthreads();   // A(s) + x visible to all warps

      // ---- B fragments: direct LDS from x tile, shifted by tap ----
      const int off = (tap / 3) * 68 + (tap % 3);
      uint32_t bfr[8];
#pragma unroll
      for (int j = 0; j < 4; j++) {
        uint32_t ca = (uint32_t)((pj[j] + off) * CS) + bOff;
        bfr[2 * j]     = *reinterpret_cast<const uint32_t*>(sxt + ca);
        bfr[2 * j + 1] = *reinterpret_cast<const uint32_t*>(sxt + ca + 16);
      }
      // ---- pass 1: w_hi ----
      uint32_t a[4][4];
#pragma unroll
      for (int f = 0; f < 4; f++)
        LDSM4(a[f][0], a[f][1], a[f][2], a[f][3],
              sab + (uint32_t)(buf * ABUF) + aRow + (uint32_t)(f * 16 * SA_B));
#pragma unroll
      for (int f = 0; f < 4; f++)
#pragma unroll
        for (int j = 0; j < 4; j++)
          MMA16816(acc[f][j], a[f], bfr[2 * j], bfr[2 * j + 1]);
      // ---- pass 2: w_lo ----
#pragma unroll
      for (int f = 0; f < 4; f++)
        LDSM4(a[f][0], a[f][1], a[f][2], a[f][3],
              sab + (uint32_t)(buf * ABUF + AHL) + aRow + (uint32_t)(f * 16 * SA_B));
#pragma unroll
      for (int f = 0; f < 4; f++)
#pragma unroll
        for (int j = 0; j < 4; j++)
          MMA16816(acc[f][j], a[f], bfr[2 * j], bfr[2 * j + 1]);
    }
  }

  // ---- epilogue: bias + store ----
  float* ob = out + (size_t)b * (NFOUT * HH * WW) + t * 128;
#pragma unroll
  for (int f = 0; f < 4; f++) {
    int fo0 = wm * 64 + f * 16 + (lane >> 2);
    float bv0 = sbias[fo0], bv1 = sbias[fo0 + 8];
#pragma unroll
    for (int j = 0; j < 4; j++) {
      int n = wn * 32 + j * 8 + 2 * (lane & 3);
      float2 v0 = make_float2(acc[f][j][0] + bv0, acc[f][j][1] + bv0);
      float2 v1 = make_float2(acc[f][j][2] + bv1, acc[f][j][3] + bv1);
      *reinterpret_cast<float2*>(ob + (size_t)fo0 * (HH * WW) + n) = v0;
      *reinterpret_cast<float2*>(ob + (size_t)(fo0 + 8) * (HH * WW) + n) = v1;
    }
  }
}

// ===========================================================================
extern "C" void kernel_launch(void* const* d_in, const int* in_sizes, int n_in,
                              void* d_out, int out_size) {
  const float* x   = (const float*)d_in[0];
  const float* lat = (const float*)d_in[1];
  const float* Wm  = (const float*)d_in[2];
  const float* bv  = (const float*)d_in[3];
  float* out = (float*)d_out;

  cudaFuncSetAttribute(hyper_gemm, cudaFuncAttributeMaxDynamicSharedMemorySize, HSMEM);

  hyper_gemm<<<(NROWS + 255) / 256, 256, HSMEM>>>(lat, Wm, bv);

  dim3 g(HH * WW / 128, NB);   // 32 x 16 = 512 CTAs
  conv_mma<<<g, 256>>>(x, out);
}

// round 10
// speedup vs baseline: 2.4687x; 1.4246x over previous
#include <cuda_runtime.h>
#include <cuda_fp16.h>
#include <cstdint>

typedef unsigned long long ull;

#define NROWS 147584
#define KSIZE 147456
#define LATD  512
#define NB    16
#define NFIN  128
#define NFOUT 128
#define HH    64
#define WW    64

// split-fp16 weights, k-reordered: k' = tap*128 + fi
__device__ __align__(16) __half g_kh[NB * KSIZE];   // 4.72 MB
__device__ __align__(16) __half g_kl[NB * KSIZE];   // 4.72 MB
__device__ float g_bias[NB * NFOUT];

// ---------------- f32x2 helpers ----------------
#define PK2(dst, a, b) \
  asm("mov.b64 %0, {%1, %2};" : "=l"(dst) : "r"(__float_as_uint(a)), "r"(__float_as_uint(b)))
#define FMA2(acc, a, b) \
  asm("fma.rn.f32x2 %0, %1, %2, %3;" : "=l"(acc) : "l"(a), "l"(b), "l"(acc))

// ---------------- cp.async ----------------
#define CPA16(dst, src) \
  asm volatile("cp.async.cg.shared.global [%0], [%1], 16;" :: "r"(dst), "l"(src))
#define CPCOMMIT() asm volatile("cp.async.commit_group;" ::: "memory")
#define CPWAIT1()  asm volatile("cp.async.wait_group 1;" ::: "memory")
#define CPWAIT0()  asm volatile("cp.async.wait_group 0;" ::: "memory")

__device__ __forceinline__ uint32_t smem_u32(const void* p) {
  uint32_t a;
  asm("{ .reg .u64 t; cvta.to.shared.u64 t, %1; cvt.u32.u64 %0, t; }" : "=r"(a) : "l"(p));
  return a;
}

// ---------------- warp-MMA helpers ----------------
#define LDSM4(r0, r1, r2, r3, addr) \
  asm volatile("ldmatrix.sync.aligned.m8n8.x4.shared.b16 {%0,%1,%2,%3}, [%4];" \
               : "=r"(r0), "=r"(r1), "=r"(r2), "=r"(r3) : "r"(addr))
#define MMA16816(c, a, b0, b1) \
  asm volatile("mma.sync.aligned.m16n8k16.row.col.f32.f16.f16.f32 " \
               "{%0,%1,%2,%3}, {%4,%5,%6,%7}, {%8,%9}, {%0,%1,%2,%3};" \
               : "+f"((c)[0]), "+f"((c)[1]), "+f"((c)[2]), "+f"((c)[3]) \
               : "r"((a)[0]), "r"((a)[1]), "r"((a)[2]), "r"((a)[3]), \
                 "r"(b0), "r"(b1))

// ===========================================================================
// Kernel A: hyper GEMM. 512 rows/block, 2 rows/thread (rows tid, tid+256).
// W staged via float4 cp.async, double-buffered; rows stride 20 floats
// (16B-aligned dst; scalar w-reads 4-way conflict - cheap, 2 per k).
// lat transposed [k][16b] in smem; 4x LDS.128 broadcast serves 16 FFMA2.
// Epilogue: split-fp16 weights in k' = tap*128+fi order + f32 bias.
// ===========================================================================
#define HKC   16
#define HRS   20                              // row stride (floats)
#define HROWS 512
#define HBUF  (HROWS * HRS)                   // floats per buffer
#define HSMEM ((2 * HBUF + LATD * 16) * 4)    // 81920 + 32768 = 114688 B

__global__ __launch_bounds__(256) void hyper_gemm(
    const float* __restrict__ lat, const float* __restrict__ Wm,
    const float* __restrict__ bias)
{
  extern __shared__ __align__(16) float hsm[];
  float* Ws = hsm;                     // [2][512][20]
  float* latc = hsm + 2 * HBUF;        // [512][16]
  const uint32_t wsb = smem_u32(Ws);
  const int tid = threadIdx.x;
  const int j0 = blockIdx.x * HROWS;

  ull acc[2][8];
#pragma unroll
  for (int r = 0; r < 2; r++)
#pragma unroll
    for (int i = 0; i < 8; i++) acc[r][i] = 0ull;

  for (int idx = tid; idx < LATD * 16; idx += 256)
    latc[idx] = lat[(idx & 15) * LATD + (idx >> 4)];

  // prologue: chunk 0 -> buf 0  (8 float4 per thread)
#pragma unroll
  for (int p = 0; p < 8; p++) {
    int idx = p * 256 + tid;
    int r = idx >> 2, q = idx & 3;
    if (j0 + r < NROWS)
      CPA16(wsb + (uint32_t)(r * HRS + q * 4) * 4,
            Wm + (size_t)(j0 + r) * LATD + q * 4);
  }
  CPCOMMIT();

  int buf = 0;
  for (int c = 0; c < LATD / HKC; c++) {
    if (c + 1 < LATD / HKC) {
#pragma unroll
      for (int p = 0; p < 8; p++) {
        int idx = p * 256 + tid;
        int r = idx >> 2, q = idx & 3;
        if (j0 + r < NROWS)
          CPA16(wsb + (uint32_t)((buf ^ 1) * HBUF + r * HRS + q * 4) * 4,
                Wm + (size_t)(j0 + r) * LATD + (c + 1) * HKC + q * 4);
      }
      CPCOMMIT();
      CPWAIT1();
    } else {
      CPWAIT0();
    }
    __syncthreads();

    const ulonglong2* latp = reinterpret_cast<const ulonglong2*>(latc);
    const float* wr0 = &Ws[buf * HBUF + tid * HRS];
    const float* wr1 = &Ws[buf * HBUF + (tid + 256) * HRS];
#pragma unroll
    for (int k = 0; k < HKC; k++) {
      float w0 = wr0[k], w1 = wr1[k];
      ull w20, w21; PK2(w20, w0, w0); PK2(w21, w1, w1);
      int kk = c * HKC + k;
#pragma unroll
      for (int q = 0; q < 4; q++) {
        ulonglong2 lv = latp[kk * 4 + q];
        FMA2(acc[0][2 * q + 0], w20, lv.x);
        FMA2(acc[0][2 * q + 1], w20, lv.y);
        FMA2(acc[1][2 * q + 0], w21, lv.x);
        FMA2(acc[1][2 * q + 1], w21, lv.y);
      }
    }
    buf ^= 1;
    __syncthreads();
  }

#pragma unroll
  for (int rr = 0; rr < 2; rr++) {
    int j = j0 + tid + rr * 256;
    if (j < KSIZE) {
      int fo = j / 1152;
      int rem = j - fo * 1152;
      int fi = rem / 9;
      int tap = rem - fi * 9;
      size_t dst = (size_t)fo * 1152 + tap * 128 + fi;
      float bv = bias[j];
#pragma unroll
      for (int p = 0; p < 8; p++) {
        float2 v = *reinterpret_cast<float2*>(&acc[rr][p]);
        float va = v.x + bv, vb = v.y + bv;
        __half ha = __float2half(va);
        __half la = __float2half(va - __half2float(ha));
        __half hb = __float2half(vb);
        __half lb = __float2half(vb - __half2float(hb));
        g_kh[(size_t)(2 * p + 0) * KSIZE + dst] = ha;
        g_kl[(size_t)(2 * p + 0) * KSIZE + dst] = la;
        g_kh[(size_t)(2 * p + 1) * KSIZE + dst] = hb;
        g_kl[(size_t)(2 * p + 1) * KSIZE + dst] = lb;
      }
    } else if (j < NROWS) {
      int fo = j - KSIZE;
      float bv = bias[j];
#pragma unroll
      for (int p = 0; p < 8; p++) {
        float2 v = *reinterpret_cast<float2*>(&acc[rr][p]);
        g_bias[(2 * p + 0) * NFOUT + fo] = v.x + bv;
        g_bias[(2 * p + 1) * NFOUT + fo] = v.y + bv;
      }
    }
  }
}

// ===========================================================================
// Kernel B: warp-MMA fp16 2-pass implicit-GEMM conv, 9-tap weight staging.
// CTA = (sample, 128-px tile). 8 warps M64xN32. Per fi-chunk (8 of 16 fi):
//   sync; cp.async ALL 9 taps' A (hi+lo, 73.7KB, XOR-swizzled 32B rows);
//   stage x tile ([4 rows x 68][16 fi], 36B cells) overlapping the cp.async;
//   wait+sync; compute 9 taps x 32 MMA with zero intervening barriers.
// 16 syncs total (was 144). A rows: off = r*32 + ((ch*16) ^ ((r&4)<<2)) ->
// ldmatrix phases conflict-free at stride 32.
// ===========================================================================
#define CS   36                       // bytes per x cell (16 fp16 + 4 pad)
#define XTB  (272 * CS)               // 9792 B
#define ATILE 4096                    // one (tap,hl) tile: 128 rows * 32 B
#define A_ALL (18 * ATILE)            // 73728 B
#define X_OFF A_ALL
#define BIAS_OFF (A_ALL + XTB)
#define CONV_SMEM (BIAS_OFF + NFOUT * 4)   // 84032 B

__global__ __launch_bounds__(256, 2) void conv_mma(
    const float* __restrict__ x, float* __restrict__ out)
{
  extern __shared__ __align__(16) unsigned char sm[];
  unsigned char* sxt = sm + X_OFF;
  float* sbias = reinterpret_cast<float*>(sm + BIAS_OFF);

  const int tid = threadIdx.x;
  const int lane = tid & 31, wid = tid >> 5;
  const int wm = wid >> 2;          // m-half (64 fouts)
  const int wn = wid & 3;           // n-quarter (32 px)
  const int t = blockIdx.x;         // out rows 2t, 2t+1
  const int b = blockIdx.y;

  float acc[4][4][4];
#pragma unroll
  for (int f = 0; f < 4; f++)
#pragma unroll
    for (int j = 0; j < 4; j++)
#pragma unroll
      for (int q = 0; q < 4; q++) acc[f][j][q] = 0.f;

  if (tid < NFOUT) sbias[tid] = g_bias[b * NFOUT + tid];

  const __half* kh = g_kh + (size_t)b * KSIZE;
  const __half* kl = g_kl + (size_t)b * KSIZE;
  const float* xb = x + (size_t)(b * NFIN) * (HH * WW);

  const uint32_t sab = smem_u32(sm);
  // per-lane ldmatrix offset within a (tap,hl) tile (row part, swizzled)
  const uint32_t aRowBase =
      (uint32_t)((wm * 64 + (lane & 15)) * 32) +
      ((uint32_t)((lane >> 4) << 4) ^ (uint32_t)((lane & 4) << 2));

  // per-lane B-fragment cell indices
  int pj[4];
#pragma unroll
  for (int j = 0; j < 4; j++) {
    int px = wn * 32 + j * 8 + (lane >> 2);
    pj[j] = (px >> 6) * 68 + (px & 63);
  }
  const uint32_t bOff = (uint32_t)((lane & 3) * 4);

  for (int fc = 0; fc < 8; fc++) {
    __syncthreads();   // previous window's A/x reads complete

    // ---- issue A: 9 taps x (hi,lo), 18 float4 per thread ----
    {
      const int kofs = fc * 16;
#pragma unroll
      for (int p = 0; p < 18; p++) {
        int i = p * 256 + tid;
        int tile = i >> 8;               // tap*2 + hl
        int rem = i & 255;
        int r = rem >> 1, ch = rem & 1;
        int tap = tile >> 1, hl = tile & 1;
        const __half* src = (hl ? kl : kh) + (size_t)r * 1152 + tap * 128 + kofs + ch * 8;
        uint32_t dst = (uint32_t)(tile * ATILE + r * 32 + ((ch << 4) ^ ((r & 4) << 2)));
        CPA16(sab + dst, src);
      }
      CPCOMMIT();
    }
    // ---- stage x tile (overlaps A cp.async) ----
    {
      const int fib = fc * 16;
#pragma unroll
      for (int p = 0; p < 17; p++) {
        int i = p * 256 + tid;
        int fi = i / 272, cell = i - fi * 272;
        int r = cell / 68, c = cell - r * 68;
        int gr = 2 * t + r;            // padded row
        float v = 0.f;
        if ((unsigned)(gr - 1) < (unsigned)HH && (unsigned)(c - 1) < (unsigned)WW)
          v = xb[(size_t)(fib + fi) * (HH * WW) + (gr - 1) * WW + (c - 1)];
        *reinterpret_cast<__half*>(sxt + cell * CS + fi * 2) = __float2half(v);
      }
    }
    CPWAIT0();
    __syncthreads();

    // ---- compute: 9 taps, no barriers ----
#pragma unroll
    for (int tap = 0; tap < 9; tap++) {
      const int off = (tap / 3) * 68 + (tap % 3);
      uint32_t bfr[8];
#pragma unroll
      for (int j = 0; j < 4; j++) {
        uint32_t ca = (uint32_t)((pj[j] + off) * CS) + bOff;
        bfr[2 * j]     = *reinterpret_cast<const uint32_t*>(sxt + ca);
        bfr[2 * j + 1] = *reinterpret_cast<const uint32_t*>(sxt + ca + 16);
      }
      const uint32_t tileH = sab + (uint32_t)(tap * 2 * ATILE) + aRowBase;
      uint32_t a[4][4];
#pragma unroll
      for (int f = 0; f < 4; f++)
        LDSM4(a[f][0], a[f][1], a[f][2], a[f][3], tileH + (uint32_t)(f * 512));
#pragma unroll
      for (int f = 0; f < 4; f++)
#pragma unroll
        for (int j = 0; j < 4; j++)
          MMA16816(acc[f][j], a[f], bfr[2 * j], bfr[2 * j + 1]);
#pragma unroll
      for (int f = 0; f < 4; f++)
        LDSM4(a[f][0], a[f][1], a[f][2], a[f][3], tileH + (uint32_t)(ATILE + f * 512));
#pragma unroll
      for (int f = 0; f < 4; f++)
#pragma unroll
        for (int j = 0; j < 4; j++)
          MMA16816(acc[f][j], a[f], bfr[2 * j], bfr[2 * j + 1]);
    }
  }

  // ---- epilogue: bias + store ----
  float* ob = out + (size_t)b * (NFOUT * HH * WW) + t * 128;
#pragma unroll
  for (int f = 0; f < 4; f++) {
    int fo0 = wm * 64 + f * 16 + (lane >> 2);
    float bv0 = sbias[fo0], bv1 = sbias[fo0 + 8];
#pragma unroll
    for (int j = 0; j < 4; j++) {
      int n = wn * 32 + j * 8 + 2 * (lane & 3);
      float2 v0 = make_float2(acc[f][j][0] + bv0, acc[f][j][1] + bv0);
      float2 v1 = make_float2(acc[f][j][2] + bv1, acc[f][j][3] + bv1);
      *reinterpret_cast<float2*>(ob + (size_t)fo0 * (HH * WW) + n) = v0;
      *reinterpret_cast<float2*>(ob + (size_t)(fo0 + 8) * (HH * WW) + n) = v1;
    }
  }
}

// ===========================================================================
extern "C" void kernel_launch(void* const* d_in, const int* in_sizes, int n_in,
                              void* d_out, int out_size) {
  const float* x   = (const float*)d_in[0];
  const float* lat = (const float*)d_in[1];
  const float* Wm  = (const float*)d_in[2];
  const float* bv  = (const float*)d_in[3];
  float* out = (float*)d_out;

  cudaFuncSetAttribute(hyper_gemm, cudaFuncAttributeMaxDynamicSharedMemorySize, HSMEM);
  cudaFuncSetAttribute(conv_mma, cudaFuncAttributeMaxDynamicSharedMemorySize, CONV_SMEM);

  hyper_gemm<<<(NROWS + HROWS - 1) / HROWS, 256, HSMEM>>>(lat, Wm, bv);

  dim3 g(HH * WW / 128, NB);   // 32 x 16 = 512 CTAs
  conv_mma<<<g, 256, CONV_SMEM>>>(x, out);
}